// round 5
// baseline (speedup 1.0000x reference)
#include <cuda_runtime.h>
#include <cuda_fp16.h>
#include <cstdint>
#include <math.h>

#define Bsz   8
#define CIN   512
#define COUT  512
#define HH    64
#define WW    64
#define KAREA 9
#define RED   (CIN*KAREA)

#define BK      32
#define NCHUNK  (KAREA*(CIN/BK))   // 144
#define XPAD_H  66
#define XROW    64
#define XPLANE  (XPAD_H*XROW)      // 4224

// ---------------- static device scratch --------------------------------------
__device__ float  g_S[Bsz*CIN];
__device__ float  g_D[Bsz*COUT];
__device__ __half g_Ah[(size_t)KAREA*COUT*CIN];        // [sh][o][i]
__device__ __half g_Xh[(size_t)3*Bsz*CIN*XPLANE];      // [kx][b][ci][y+1][x], pads stay 0

// ---------------- helpers ------------------------------------------------------
__device__ __forceinline__ uint32_t smem_u32(const void* p){
    uint32_t a;
    asm("{ .reg .u64 t; cvta.to.shared.u64 t, %1; cvt.u32.u64 %0, t; }" : "=r"(a) : "l"(p));
    return a;
}
__device__ __forceinline__ void cp16(uint32_t dst, const void* src){
    asm volatile("cp.async.cg.shared.global [%0], [%1], 16;" :: "r"(dst), "l"(src));
}
__device__ __forceinline__ void ldsm_x4(uint32_t* r, uint32_t addr){
    asm volatile("ldmatrix.sync.aligned.m8n8.x4.shared.b16 {%0,%1,%2,%3}, [%4];"
                 : "=r"(r[0]),"=r"(r[1]),"=r"(r[2]),"=r"(r[3]) : "r"(addr));
}
__device__ __forceinline__ void ldsm_x4t(uint32_t* r, uint32_t addr){
    asm volatile("ldmatrix.sync.aligned.m8n8.x4.trans.shared.b16 {%0,%1,%2,%3}, [%4];"
                 : "=r"(r[0]),"=r"(r[1]),"=r"(r[2]),"=r"(r[3]) : "r"(addr));
}
__device__ __forceinline__ void mma_f16(float* c, const uint32_t* a, const uint32_t* b){
    asm volatile("mma.sync.aligned.m16n8k16.row.col.f32.f16.f16.f32 "
        "{%0,%1,%2,%3}, {%4,%5,%6,%7}, {%8,%9}, {%0,%1,%2,%3};"
        : "+f"(c[0]),"+f"(c[1]),"+f"(c[2]),"+f"(c[3])
        : "r"(a[0]),"r"(a[1]),"r"(a[2]),"r"(a[3]), "r"(b[0]),"r"(b[1]));
}

// ---------------- prep kernels ------------------------------------------------
__global__ void k_style(const float* __restrict__ style, const float* __restrict__ mw){
    __shared__ float st[CIN];
    int b = blockIdx.x;
    st[threadIdx.x] = style[b*CIN + threadIdx.x];
    __syncthreads();
    const float* row = mw + (size_t)threadIdx.x*CIN;
    float acc = 0.f;
#pragma unroll 8
    for (int j = 0; j < CIN; j++) acc += row[j]*st[j];
    g_S[b*CIN + threadIdx.x] = acc;
}

__global__ void k_demod(const float* __restrict__ w){
    int gw   = blockIdx.x*8 + (threadIdx.x >> 5);
    int lane = threadIdx.x & 31;
    int b = gw >> 9, o = gw & 511;
    const float* wr = w + (size_t)o*RED;
    const float* sr = g_S + b*CIN;
    float sum = 0.f;
    for (int idx = lane; idx < RED; idx += 32){
        float m = wr[idx]*sr[idx/9];
        sum += m*m;
    }
#pragma unroll
    for (int off = 16; off; off >>= 1) sum += __shfl_xor_sync(~0u, sum, off);
    if (!lane)
        g_D[gw] = rsqrtf((float)RED) * rsqrtf(sum/(float)RED + 1e-8f);
}

__global__ void k_packw(const float* __restrict__ w){
    int gid = blockIdx.x*256 + threadIdx.x;
    int i = gid & 511;
    int o = (gid >> 9) & 511;
    int k = gid >> 18;
    g_Ah[((size_t)k*COUT + o)*CIN + i] = __float2half_rn(w[((size_t)o*CIN + i)*KAREA + k]);
}

__global__ void k_prepx(const float* __restrict__ x){
    int gid = blockIdx.x*256 + threadIdx.x;
    int xc = gid & 63;
    int y  = (gid >> 6) & 63;
    int ci = (gid >> 12) & 511;
    int b  = gid >> 21;
    __half v = __float2half_rn(x[gid] * g_S[b*CIN + ci]);
    size_t planeBase = ((size_t)b*CIN + ci)*XPLANE + (size_t)(y+1)*XROW;
    const size_t kxStride = (size_t)Bsz*CIN*XPLANE;
#pragma unroll
    for (int kx = 0; kx < 3; kx++){
        int dx = xc + 1 - kx;
        if (dx >= 0 && dx < 64)
            g_Xh[(size_t)kx*kxStride + planeBase + dx] = v;
    }
}

// ---------------- main mma.sync kernel ------------------------------------------
// CTA: 128 couts x 256 px (4 image rows). 8 warps (2m x 4n), warp tile 64x64.
// 4-stage cp.async pipeline, one __syncthreads per chunk.

#define APAD   40                    // halfs per A smem row (80B)
#define BPAD   264                   // halfs per B smem row (528B)
#define A_ST   (128*APAD*2)          // 10240 B
#define B_ST   (BK*BPAD*2)           // 16896 B
#define STAGE  (A_ST + B_ST)         // 27136 B
#define NSTAGE 4
#define SMEM_SZ (NSTAGE*STAGE)       // 108544 B

__global__ void __launch_bounds__(256, 1)
k_conv_mma(float* __restrict__ out)
{
    extern __shared__ __align__(16) char smraw[];
    const uint32_t s0 = smem_u32(smraw);

    const int tid  = threadIdx.x;
    const int lane = tid & 31;
    const int wid  = tid >> 5;
    const int wm   = wid >> 2;           // 0..1
    const int wn   = wid & 3;            // 0..3

    const int b   = blockIdx.z;
    const int co0 = blockIdx.y << 7;     // cout tile base (128)
    const int y0  = blockIdx.x << 2;     // 4 image rows (256 px)

    float acc[4][8][4];
#pragma unroll
    for (int mt = 0; mt < 4; mt++)
#pragma unroll
        for (int nt = 0; nt < 8; nt++)
#pragma unroll
            for (int r = 0; r < 4; r++) acc[mt][nt][r] = 0.f;

    // ---- chunk loader: A 128x32 (K-major), B 32x256 px ----
    auto load_chunk = [&](int ch, int buf){
        int sh  = ch >> 4;
        int ci0 = (ch & 15) << 5;
        int ky  = sh / 3;
        int kx  = sh - ky*3;
        const __half* aSrc = g_Ah + ((size_t)sh*COUT + co0)*CIN + ci0;
        const __half* xSrc = g_Xh + (((size_t)kx*Bsz + b)*CIN + ci0)*XPLANE
                           + (size_t)(y0 + ky)*XROW;
        uint32_t dA = s0 + buf*STAGE;
        uint32_t dB = dA + A_ST;
#pragma unroll
        for (int it = 0; it < 6; it++){
            int idx = tid + (it << 8);
            if (idx < 512){                       // A: 128 rows x 64B
                int m = idx >> 2, q = idx & 3;
                cp16(dA + m*(APAD*2) + q*16, aSrc + (size_t)m*CIN + (q<<3));
            } else {                              // B: 32 rows x 512B (4 y-rows)
                int i2 = idx - 512;               // 0..1023
                int k  = i2 >> 5;
                int q  = i2 & 31;
                cp16(dB + k*(BPAD*2) + q*16, xSrc + (size_t)k*XPLANE + (q<<3));
            }
        }
        asm volatile("cp.async.commit_group;");
    };

    load_chunk(0, 0);
    load_chunk(1, 1);
    load_chunk(2, 2);

    for (int c = 0; c < NCHUNK; c++){
        if (c <= NCHUNK-3)      asm volatile("cp.async.wait_group 2;");
        else if (c == NCHUNK-2) asm volatile("cp.async.wait_group 1;");
        else                    asm volatile("cp.async.wait_group 0;");
        __syncthreads();

        if (c + 3 < NCHUNK) load_chunk(c+3, (c+3) & 3);

        const uint32_t aBase = s0 + (c & 3)*STAGE;
        const uint32_t bBase = aBase + A_ST;
#pragma unroll
        for (int ks = 0; ks < 2; ks++){
            uint32_t afr[4][4], bfr[4][4];
#pragma unroll
            for (int mt = 0; mt < 4; mt++){
                int row = wm*64 + mt*16 + (lane & 15);
                int col = ks*16 + ((lane >> 4) << 3);
                ldsm_x4(afr[mt], aBase + (row*APAD + col)*2);
            }
#pragma unroll
            for (int np = 0; np < 4; np++){
                int g  = lane >> 3;
                int lr = lane & 7;
                int row = ks*16 + ((g & 1) << 3) + lr;
                int col = wn*64 + np*16 + ((g >> 1) << 3);
                ldsm_x4t(bfr[np], bBase + (row*BPAD + col)*2);
            }
#pragma unroll
            for (int mt = 0; mt < 4; mt++)
#pragma unroll
                for (int nt = 0; nt < 8; nt++)
                    mma_f16(acc[mt][nt], afr[mt], &bfr[nt>>1][(nt&1)*2]);
        }
    }

    // ---- epilogue: scale*demod, store ----
    const int row0 = lane >> 2;
    const int col0 = (lane & 3) << 1;
#pragma unroll
    for (int mt = 0; mt < 4; mt++){
        int cout_a = co0 + wm*64 + mt*16 + row0;
        int cout_b = cout_a + 8;
        float dva = g_D[b*COUT + cout_a];
        float dvb = g_D[b*COUT + cout_b];
        float* opa = out + ((size_t)(b*COUT + cout_a)*HH + y0)*WW;
        float* opb = out + ((size_t)(b*COUT + cout_b)*HH + y0)*WW;
#pragma unroll
        for (int nt = 0; nt < 8; nt++){
            int n  = wn*64 + nt*8 + col0;   // 0..255
            int yy = n >> 6;
            int xx = n & 63;
            float2 va, vb;
            va.x = acc[mt][nt][0]*dva; va.y = acc[mt][nt][1]*dva;
            vb.x = acc[mt][nt][2]*dvb; vb.y = acc[mt][nt][3]*dvb;
            *(float2*)(opa + (size_t)yy*WW + xx) = va;
            *(float2*)(opb + (size_t)yy*WW + xx) = vb;
        }
    }
}

// ---------------- launch --------------------------------------------------------
extern "C" void kernel_launch(void* const* d_in, const int* in_sizes, int n_in,
                              void* d_out, int out_size) {
    const float *x = nullptr, *style = nullptr, *weight = nullptr, *mod_w = nullptr;
    for (int i = 0; i < n_in; i++){
        switch (in_sizes[i]){
            case Bsz*CIN*HH*WW:   x      = (const float*)d_in[i]; break;
            case Bsz*CIN:         style  = (const float*)d_in[i]; break;
            case COUT*CIN*KAREA:  weight = (const float*)d_in[i]; break;
            case CIN*CIN:         mod_w  = (const float*)d_in[i]; break;
        }
    }
    float* out = (float*)d_out;

    cudaFuncSetAttribute(k_conv_mma, cudaFuncAttributeMaxDynamicSharedMemorySize, SMEM_SZ);

    k_style<<<Bsz, CIN>>>(style, mod_w);
    k_demod<<<(Bsz*COUT)/8, 256>>>(weight);
    k_packw<<<(KAREA*COUT*CIN)/256, 256>>>(weight);
    k_prepx<<<(Bsz*CIN*HH*WW)/256, 256>>>(x);

    dim3 grid(HH/4, COUT/128, Bsz);      // 16 x 4 x 8 = 512 CTAs
    k_conv_mma<<<grid, 256, SMEM_SZ>>>(out);
}

// round 6
// speedup vs baseline: 1.2836x; 1.2836x over previous
#include <cuda_runtime.h>
#include <cuda_fp16.h>
#include <cstdint>
#include <math.h>

#define Bsz   8
#define CIN   512
#define COUT  512
#define HH    64
#define WW    64
#define KAREA 9
#define RED   (CIN*KAREA)

#define BK      32
#define NCHUNK  (KAREA*(CIN/BK))   // 144
#define XPAD_H  66
#define XROW    64
#define XPLANE  (XPAD_H*XROW)      // 4224

// ---------------- static device scratch --------------------------------------
__device__ float  g_S[Bsz*CIN];
__device__ float  g_D[Bsz*COUT];
__device__ __half g_Ah[(size_t)KAREA*COUT*CIN];        // [sh][o][i]
__device__ __half g_Xh[(size_t)3*Bsz*CIN*XPLANE];      // [kx][b][ci][y+1][x], pads stay 0

// ---------------- helpers ------------------------------------------------------
__device__ __forceinline__ uint32_t smem_u32(const void* p){
    uint32_t a;
    asm("{ .reg .u64 t; cvta.to.shared.u64 t, %1; cvt.u32.u64 %0, t; }" : "=r"(a) : "l"(p));
    return a;
}
__device__ __forceinline__ void cp16(uint32_t dst, const void* src){
    asm volatile("cp.async.cg.shared.global [%0], [%1], 16;" :: "r"(dst), "l"(src));
}
__device__ __forceinline__ void ldsm_x4(uint32_t* r, uint32_t addr){
    asm volatile("ldmatrix.sync.aligned.m8n8.x4.shared.b16 {%0,%1,%2,%3}, [%4];"
                 : "=r"(r[0]),"=r"(r[1]),"=r"(r[2]),"=r"(r[3]) : "r"(addr));
}
__device__ __forceinline__ void ldsm_x4t(uint32_t* r, uint32_t addr){
    asm volatile("ldmatrix.sync.aligned.m8n8.x4.trans.shared.b16 {%0,%1,%2,%3}, [%4];"
                 : "=r"(r[0]),"=r"(r[1]),"=r"(r[2]),"=r"(r[3]) : "r"(addr));
}
__device__ __forceinline__ void mma_f16(float* c, const uint32_t* a, const uint32_t* b){
    asm volatile("mma.sync.aligned.m16n8k16.row.col.f32.f16.f16.f32 "
        "{%0,%1,%2,%3}, {%4,%5,%6,%7}, {%8,%9}, {%0,%1,%2,%3};"
        : "+f"(c[0]),"+f"(c[1]),"+f"(c[2]),"+f"(c[3])
        : "r"(a[0]),"r"(a[1]),"r"(a[2]),"r"(a[3]), "r"(b[0]),"r"(b[1]));
}
__device__ __forceinline__ uint32_t h2pack(__half a, __half b){
    __half2 t = __halves2half2(a, b);
    return *(uint32_t*)&t;
}

// ---------------- prep kernels ------------------------------------------------
__global__ void k_style(const float* __restrict__ style, const float* __restrict__ mw){
    __shared__ float st[CIN];
    int b = blockIdx.x;
    st[threadIdx.x] = style[b*CIN + threadIdx.x];
    __syncthreads();
    const float* row = mw + (size_t)threadIdx.x*CIN;
    float acc = 0.f;
#pragma unroll 8
    for (int j = 0; j < CIN; j++) acc += row[j]*st[j];
    g_S[b*CIN + threadIdx.x] = acc;
}

__global__ void k_demod(const float* __restrict__ w){
    int gw   = blockIdx.x*8 + (threadIdx.x >> 5);
    int lane = threadIdx.x & 31;
    int b = gw >> 9, o = gw & 511;
    const float* wr = w + (size_t)o*RED;
    const float* sr = g_S + b*CIN;
    float sum = 0.f;
    for (int idx = lane; idx < RED; idx += 32){
        float m = wr[idx]*sr[idx/9];
        sum += m*m;
    }
#pragma unroll
    for (int off = 16; off; off >>= 1) sum += __shfl_xor_sync(~0u, sum, off);
    if (!lane)
        g_D[gw] = rsqrtf((float)RED) * rsqrtf(sum/(float)RED + 1e-8f);
}

__global__ void k_packw(const float* __restrict__ w){
    int gid = blockIdx.x*256 + threadIdx.x;
    int i = gid & 511;
    int o = (gid >> 9) & 511;
    int k = gid >> 18;
    g_Ah[((size_t)k*COUT + o)*CIN + i] = __float2half_rn(w[((size_t)o*CIN + i)*KAREA + k]);
}

// vectorized: 8 px/thread, all stores aligned uint4, shuffles for shift edges
__global__ void k_prepx(const float* __restrict__ x){
    int gid = blockIdx.x*256 + threadIdx.x;
    int t  = gid & 7;               // 8-px segment within row (matches lane&7)
    int y  = (gid >> 3) & 63;
    int ci = (gid >> 9) & 511;
    int b  = gid >> 18;
    float s = g_S[b*CIN + ci];
    const float4* src = (const float4*)(x + (((size_t)(b*CIN + ci)*64 + y)<<6) + (t<<3));
    float4 f0 = src[0], f1 = src[1];
    float v0=f0.x*s, v1=f0.y*s, v2=f0.z*s, v3=f0.w*s;
    float v4=f1.x*s, v5=f1.y*s, v6=f1.z*s, v7=f1.w*s;
    __half h0=__float2half_rn(v0), h1=__float2half_rn(v1),
           h2=__float2half_rn(v2), h3=__float2half_rn(v3),
           h4=__float2half_rn(v4), h5=__float2half_rn(v5),
           h6=__float2half_rn(v6), h7=__float2half_rn(v7);
    float pl = __shfl_up_sync(~0u,  v7, 1);
    float nf = __shfl_down_sync(~0u, v0, 1);
    __half hpl = (t==0) ? __float2half_rn(0.f) : __float2half_rn(pl);
    __half hnf = (t==7) ? __float2half_rn(0.f) : __float2half_rn(nf);

    size_t rowOff = (size_t)(b*CIN + ci)*XPLANE + (size_t)(y+1)*XROW + (t<<3);
    const size_t kxStride = (size_t)Bsz*CIN*XPLANE;
    uint4 c1 = { h2pack(h0,h1), h2pack(h2,h3), h2pack(h4,h5), h2pack(h6,h7) }; // kx=1
    uint4 c0 = { h2pack(hpl,h0), h2pack(h1,h2), h2pack(h3,h4), h2pack(h5,h6) };// kx=0
    uint4 c2 = { h2pack(h1,h2), h2pack(h3,h4), h2pack(h5,h6), h2pack(h7,hnf) };// kx=2
    *(uint4*)(g_Xh + rowOff)              = c0;
    *(uint4*)(g_Xh + kxStride + rowOff)   = c1;
    *(uint4*)(g_Xh + 2*kxStride + rowOff) = c2;
}

// ---------------- main mma.sync kernel ------------------------------------------
// CTA: 128 couts x 128 px (2 image rows). 8 warps (2m x 4n), warp tile 64x32.
// 4-stage cp.async pipeline, ONE __syncthreads per chunk.

#define APAD   40                    // halfs per A smem row (80B)
#define BPAD   136                   // halfs per B smem row (272B)
#define A_ST   (128*APAD*2)          // 10240 B
#define B_ST   (BK*BPAD*2)           // 8704 B
#define STAGE  (A_ST + B_ST)         // 18944 B
#define SMEM_SZ (4*STAGE)            // 75776 B

__global__ void __launch_bounds__(256, 2)
k_conv_mma(float* __restrict__ out)
{
    extern __shared__ __align__(16) char smraw[];
    const uint32_t s0 = smem_u32(smraw);

    const int tid  = threadIdx.x;
    const int lane = tid & 31;
    const int wid  = tid >> 5;
    const int wm   = wid >> 2;           // 0..1
    const int wn   = wid & 3;            // 0..3

    const int b   = blockIdx.z;
    const int co0 = blockIdx.y << 7;     // cout tile base
    const int y0  = blockIdx.x << 1;     // 2 image rows (128 px)

    float acc[4][4][4];
#pragma unroll
    for (int mt = 0; mt < 4; mt++)
#pragma unroll
        for (int nt = 0; nt < 4; nt++)
#pragma unroll
            for (int r = 0; r < 4; r++) acc[mt][nt][r] = 0.f;

    auto load_chunk = [&](int ch, int buf){
        int sh  = ch >> 4;
        int ci0 = (ch & 15) << 5;
        int ky  = sh / 3;
        int kx  = sh - ky*3;
        const __half* aSrc = g_Ah + ((size_t)sh*COUT + co0)*CIN + ci0;
        const __half* xSrc = g_Xh + (((size_t)kx*Bsz + b)*CIN + ci0)*XPLANE
                           + (size_t)(y0 + ky)*XROW;
        uint32_t dA = s0 + buf*STAGE;
        uint32_t dB = dA + A_ST;
#pragma unroll
        for (int it = 0; it < 4; it++){
            int idx = tid + (it << 8);
            if (idx < 512){                       // A: 128 rows x 64B
                int m = idx >> 2, q = idx & 3;
                cp16(dA + m*(APAD*2) + q*16, aSrc + (size_t)m*CIN + (q<<3));
            } else {                              // B: 32 rows x 256B (2 y-rows)
                int i2 = idx - 512;
                int k  = i2 >> 4;
                int q  = i2 & 15;
                cp16(dB + k*(BPAD*2) + q*16, xSrc + (size_t)k*XPLANE + (q<<3));
            }
        }
        asm volatile("cp.async.commit_group;");
    };

    load_chunk(0, 0);
    load_chunk(1, 1);
    load_chunk(2, 2);

    for (int c = 0; c < NCHUNK; c++){
        if (c < NCHUNK-2)       asm volatile("cp.async.wait_group 2;");
        else if (c == NCHUNK-2) asm volatile("cp.async.wait_group 1;");
        else                    asm volatile("cp.async.wait_group 0;");
        __syncthreads();          // chunk c visible to all; buffer (c+3)&3 == (c-1)&3 free

        if (c + 3 < NCHUNK) load_chunk(c+3, (c+3) & 3);

        const uint32_t aBase = s0 + (c & 3)*STAGE;
        const uint32_t bBase = aBase + A_ST;
#pragma unroll
        for (int ks = 0; ks < 2; ks++){
            uint32_t afr[4][4], bfr[2][4];
#pragma unroll
            for (int mt = 0; mt < 4; mt++){
                int row = wm*64 + mt*16 + (lane & 15);
                int col = ks*16 + ((lane >> 4) << 3);
                ldsm_x4(afr[mt], aBase + (row*APAD + col)*2);
            }
#pragma unroll
            for (int np = 0; np < 2; np++){
                int g  = lane >> 3;
                int lr = lane & 7;
                int row = ks*16 + ((g & 1) << 3) + lr;
                int col = wn*32 + np*16 + ((g >> 1) << 3);
                ldsm_x4t(bfr[np], bBase + (row*BPAD + col)*2);
            }
#pragma unroll
            for (int mt = 0; mt < 4; mt++)
#pragma unroll
                for (int nt = 0; nt < 4; nt++)
                    mma_f16(acc[mt][nt], afr[mt], &bfr[nt>>1][(nt&1)*2]);
        }
    }

    // ---- epilogue: scale*demod, store ----
    const int row0 = lane >> 2;
    const int col0 = (lane & 3) << 1;
#pragma unroll
    for (int mt = 0; mt < 4; mt++){
        int cout_a = co0 + wm*64 + mt*16 + row0;
        int cout_b = cout_a + 8;
        float dva = g_D[b*COUT + cout_a];
        float dvb = g_D[b*COUT + cout_b];
        float* opa = out + ((size_t)(b*COUT + cout_a)*HH + y0)*WW;
        float* opb = out + ((size_t)(b*COUT + cout_b)*HH + y0)*WW;
#pragma unroll
        for (int nt = 0; nt < 4; nt++){
            int n  = wn*32 + nt*8 + col0;
            int yy = n >> 6;
            int xx = n & 63;
            float2 va, vb;
            va.x = acc[mt][nt][0]*dva; va.y = acc[mt][nt][1]*dva;
            vb.x = acc[mt][nt][2]*dvb; vb.y = acc[mt][nt][3]*dvb;
            *(float2*)(opa + (size_t)yy*WW + xx) = va;
            *(float2*)(opb + (size_t)yy*WW + xx) = vb;
        }
    }
}

// ---------------- launch --------------------------------------------------------
extern "C" void kernel_launch(void* const* d_in, const int* in_sizes, int n_in,
                              void* d_out, int out_size) {
    const float *x = nullptr, *style = nullptr, *weight = nullptr, *mod_w = nullptr;
    for (int i = 0; i < n_in; i++){
        switch (in_sizes[i]){
            case Bsz*CIN*HH*WW:   x      = (const float*)d_in[i]; break;
            case Bsz*CIN:         style  = (const float*)d_in[i]; break;
            case COUT*CIN*KAREA:  weight = (const float*)d_in[i]; break;
            case CIN*CIN:         mod_w  = (const float*)d_in[i]; break;
        }
    }
    float* out = (float*)d_out;

    cudaFuncSetAttribute(k_conv_mma, cudaFuncAttributeMaxDynamicSharedMemorySize, SMEM_SZ);

    k_style<<<Bsz, CIN>>>(style, mod_w);
    k_demod<<<(Bsz*COUT)/8, 256>>>(weight);
    k_packw<<<(KAREA*COUT*CIN)/256, 256>>>(weight);
    k_prepx<<<(Bsz*CIN*HH*WW)/(8*256), 256>>>(x);

    dim3 grid(HH/2, COUT/128, Bsz);      // 32 x 4 x 8 = 1024 CTAs
    k_conv_mma<<<grid, 256, SMEM_SZ>>>(out);
}

// round 7
// speedup vs baseline: 1.3279x; 1.0345x over previous
#include <cuda_runtime.h>
#include <cuda_fp16.h>
#include <cstdint>
#include <math.h>

#define Bsz   8
#define CIN   512
#define COUT  512
#define HH    64
#define WW    64
#define KAREA 9
#define RED   (CIN*KAREA)

#define BK      64
#define NCHUNK  (KAREA*(CIN/BK))   // 72
#define XPAD_H  66
#define XROW    64
#define XPLANE  (XPAD_H*XROW)      // 4224

// ---------------- static device scratch --------------------------------------
__device__ float  g_S[Bsz*CIN];
__device__ float  g_D[Bsz*COUT];
__device__ __half g_Ah[(size_t)KAREA*COUT*CIN];        // [sh][o][i]
__device__ __half g_Xh[(size_t)3*Bsz*CIN*XPLANE];      // [kx][b][ci][y+1][x], pads stay 0

// ---------------- helpers ------------------------------------------------------
__device__ __forceinline__ uint32_t smem_u32(const void* p){
    uint32_t a;
    asm("{ .reg .u64 t; cvta.to.shared.u64 t, %1; cvt.u32.u64 %0, t; }" : "=r"(a) : "l"(p));
    return a;
}
__device__ __forceinline__ void cp16(uint32_t dst, const void* src){
    asm volatile("cp.async.cg.shared.global [%0], [%1], 16;" :: "r"(dst), "l"(src));
}
__device__ __forceinline__ void ldsm_x4(uint32_t* r, uint32_t addr){
    asm volatile("ldmatrix.sync.aligned.m8n8.x4.shared.b16 {%0,%1,%2,%3}, [%4];"
                 : "=r"(r[0]),"=r"(r[1]),"=r"(r[2]),"=r"(r[3]) : "r"(addr));
}
__device__ __forceinline__ void ldsm_x4t(uint32_t* r, uint32_t addr){
    asm volatile("ldmatrix.sync.aligned.m8n8.x4.trans.shared.b16 {%0,%1,%2,%3}, [%4];"
                 : "=r"(r[0]),"=r"(r[1]),"=r"(r[2]),"=r"(r[3]) : "r"(addr));
}
__device__ __forceinline__ void mma_f16(float* c, const uint32_t* a, const uint32_t* b){
    asm volatile("mma.sync.aligned.m16n8k16.row.col.f32.f16.f16.f32 "
        "{%0,%1,%2,%3}, {%4,%5,%6,%7}, {%8,%9}, {%0,%1,%2,%3};"
        : "+f"(c[0]),"+f"(c[1]),"+f"(c[2]),"+f"(c[3])
        : "r"(a[0]),"r"(a[1]),"r"(a[2]),"r"(a[3]), "r"(b[0]),"r"(b[1]));
}
__device__ __forceinline__ uint32_t h2pack(__half a, __half b){
    __half2 t = __halves2half2(a, b);
    return *(uint32_t*)&t;
}

// ---------------- prep kernel 1: style modulation -----------------------------
__global__ void k_style(const float* __restrict__ style, const float* __restrict__ mw){
    __shared__ float st[CIN];
    int b = blockIdx.x;
    st[threadIdx.x] = style[b*CIN + threadIdx.x];
    __syncthreads();
    const float* row = mw + (size_t)threadIdx.x*CIN;
    float acc = 0.f;
#pragma unroll 8
    for (int j = 0; j < CIN; j++) acc += row[j]*st[j];
    g_S[b*CIN + threadIdx.x] = acc;
}

// ---------------- prep kernel 2: fused packw | prepx | demod -------------------
#define PACKW_BLKS ((KAREA*COUT*CIN)/256)          // 9216
#define PREPX_BLKS ((Bsz*CIN*HH*WW)/(8*256))       // 8192
#define DEMOD_BLKS ((Bsz*COUT)/8)                  // 512

__global__ void k_prep2(const float* __restrict__ w, const float* __restrict__ x){
    int blk = blockIdx.x;
    if (blk < PACKW_BLKS){
        int gid = blk*256 + threadIdx.x;
        int i = gid & 511;
        int o = (gid >> 9) & 511;
        int k = gid >> 18;
        g_Ah[((size_t)k*COUT + o)*CIN + i] = __float2half_rn(w[((size_t)o*CIN + i)*KAREA + k]);
        return;
    }
    blk -= PACKW_BLKS;
    if (blk < PREPX_BLKS){
        int gid = blk*256 + threadIdx.x;
        int t  = gid & 7;
        int y  = (gid >> 3) & 63;
        int ci = (gid >> 9) & 511;
        int b  = gid >> 18;
        float s = g_S[b*CIN + ci];
        const float4* src = (const float4*)(x + (((size_t)(b*CIN + ci)*64 + y)<<6) + (t<<3));
        float4 f0 = src[0], f1 = src[1];
        float v0=f0.x*s, v1=f0.y*s, v2=f0.z*s, v3=f0.w*s;
        float v4=f1.x*s, v5=f1.y*s, v6=f1.z*s, v7=f1.w*s;
        __half h0=__float2half_rn(v0), h1=__float2half_rn(v1),
               h2=__float2half_rn(v2), h3=__float2half_rn(v3),
               h4=__float2half_rn(v4), h5=__float2half_rn(v5),
               h6=__float2half_rn(v6), h7=__float2half_rn(v7);
        float pl = __shfl_up_sync(~0u,  v7, 1);
        float nf = __shfl_down_sync(~0u, v0, 1);
        __half hpl = (t==0) ? __float2half_rn(0.f) : __float2half_rn(pl);
        __half hnf = (t==7) ? __float2half_rn(0.f) : __float2half_rn(nf);
        size_t rowOff = (size_t)(b*CIN + ci)*XPLANE + (size_t)(y+1)*XROW + (t<<3);
        const size_t kxStride = (size_t)Bsz*CIN*XPLANE;
        uint4 c1 = { h2pack(h0,h1), h2pack(h2,h3), h2pack(h4,h5), h2pack(h6,h7) };
        uint4 c0 = { h2pack(hpl,h0), h2pack(h1,h2), h2pack(h3,h4), h2pack(h5,h6) };
        uint4 c2 = { h2pack(h1,h2), h2pack(h3,h4), h2pack(h5,h6), h2pack(h7,hnf) };
        *(uint4*)(g_Xh + rowOff)              = c0;
        *(uint4*)(g_Xh + kxStride + rowOff)   = c1;
        *(uint4*)(g_Xh + 2*kxStride + rowOff) = c2;
        return;
    }
    blk -= PREPX_BLKS;
    {   // demod: one warp per (b,o)
        int gw   = blk*8 + (threadIdx.x >> 5);
        int lane = threadIdx.x & 31;
        int b = gw >> 9, o = gw & 511;
        const float* wr = w + (size_t)o*RED;
        const float* sr = g_S + b*CIN;
        float sum = 0.f;
        for (int idx = lane; idx < RED; idx += 32){
            float m = wr[idx]*sr[idx/9];
            sum += m*m;
        }
#pragma unroll
        for (int off = 16; off; off >>= 1) sum += __shfl_xor_sync(~0u, sum, off);
        if (!lane)
            g_D[gw] = rsqrtf((float)RED) * rsqrtf(sum/(float)RED + 1e-8f);
    }
}

// ---------------- main mma.sync kernel ------------------------------------------
// CTA: 128 couts x 128 px (2 image rows). 8 warps (2m x 4n), warp tile 64x32.
// BK=64, 72 chunks, 3-stage cp.async pipeline, ONE __syncthreads per chunk.

#define APAD   72                    // halfs per A smem row (144B; rows shift 16B mod 128)
#define BPAD   136                   // halfs per B smem row (272B)
#define A_ST   (128*APAD*2)          // 18432 B
#define B_ST   (BK*BPAD*2)           // 17408 B
#define STAGE  (A_ST + B_ST)         // 35840 B
#define SMEM_SZ (3*STAGE)            // 107520 B

__global__ void __launch_bounds__(256, 2)
k_conv_mma(float* __restrict__ out)
{
    extern __shared__ __align__(16) char smraw[];
    const uint32_t s0 = smem_u32(smraw);

    const int tid  = threadIdx.x;
    const int lane = tid & 31;
    const int wid  = tid >> 5;
    const int wm   = wid >> 2;           // 0..1
    const int wn   = wid & 3;            // 0..3

    const int b   = blockIdx.z;
    const int co0 = blockIdx.y << 7;     // cout tile base
    const int y0  = blockIdx.x << 1;     // 2 image rows (128 px)

    float acc[4][4][4];
#pragma unroll
    for (int mt = 0; mt < 4; mt++)
#pragma unroll
        for (int nt = 0; nt < 4; nt++)
#pragma unroll
            for (int r = 0; r < 4; r++) acc[mt][nt][r] = 0.f;

    auto load_chunk = [&](int ch, int buf){
        int sh  = ch >> 3;                // 9 shifts x 8 cin-chunks
        int ci0 = (ch & 7) << 6;
        int ky  = sh / 3;
        int kx  = sh - ky*3;
        const __half* aSrc = g_Ah + ((size_t)sh*COUT + co0)*CIN + ci0;
        const __half* xSrc = g_Xh + (((size_t)kx*Bsz + b)*CIN + ci0)*XPLANE
                           + (size_t)(y0 + ky)*XROW;
        uint32_t dA = s0 + buf*STAGE;
        uint32_t dB = dA + A_ST;
#pragma unroll
        for (int it = 0; it < 8; it++){
            int idx = tid + (it << 8);
            if (idx < 1024){                      // A: 128 rows x 128B
                int m = idx >> 3, q = idx & 7;
                cp16(dA + m*(APAD*2) + q*16, aSrc + (size_t)m*CIN + (q<<3));
            } else {                              // B: 64 rows x 256B
                int i2 = idx - 1024;
                int k  = i2 >> 4;
                int q  = i2 & 15;
                cp16(dB + k*(BPAD*2) + q*16, xSrc + (size_t)k*XPLANE + (q<<3));
            }
        }
        asm volatile("cp.async.commit_group;");
    };

    load_chunk(0, 0);
    load_chunk(1, 1);

    for (int c = 0; c < NCHUNK; c++){
        if (c < NCHUNK-1) asm volatile("cp.async.wait_group 1;");
        else              asm volatile("cp.async.wait_group 0;");
        __syncthreads();          // chunk c visible; buffer (c+2)%3 == (c-1)%3 free

        if (c + 2 < NCHUNK) load_chunk(c+2, (c+2) % 3);

        const uint32_t aBase = s0 + (c % 3)*STAGE;
        const uint32_t bBase = aBase + A_ST;
#pragma unroll
        for (int ks = 0; ks < 4; ks++){
            uint32_t afr[4][4], bfr[2][4];
#pragma unroll
            for (int mt = 0; mt < 4; mt++){
                int row = wm*64 + mt*16 + (lane & 15);
                int col = ks*16 + ((lane >> 4) << 3);
                ldsm_x4(afr[mt], aBase + (row*APAD + col)*2);
            }
#pragma unroll
            for (int np = 0; np < 2; np++){
                int g  = lane >> 3;
                int lr = lane & 7;
                int row = ks*16 + ((g & 1) << 3) + lr;
                int col = wn*32 + np*16 + ((g >> 1) << 3);
                ldsm_x4t(bfr[np], bBase + (row*BPAD + col)*2);
            }
#pragma unroll
            for (int mt = 0; mt < 4; mt++)
#pragma unroll
                for (int nt = 0; nt < 4; nt++)
                    mma_f16(acc[mt][nt], afr[mt], &bfr[nt>>1][(nt&1)*2]);
        }
    }

    // ---- epilogue: scale*demod, store ----
    const int row0 = lane >> 2;
    const int col0 = (lane & 3) << 1;
#pragma unroll
    for (int mt = 0; mt < 4; mt++){
        int cout_a = co0 + wm*64 + mt*16 + row0;
        int cout_b = cout_a + 8;
        float dva = g_D[b*COUT + cout_a];
        float dvb = g_D[b*COUT + cout_b];
        float* opa = out + ((size_t)(b*COUT + cout_a)*HH + y0)*WW;
        float* opb = out + ((size_t)(b*COUT + cout_b)*HH + y0)*WW;
#pragma unroll
        for (int nt = 0; nt < 4; nt++){
            int n  = wn*32 + nt*8 + col0;
            int yy = n >> 6;
            int xx = n & 63;
            float2 va, vb;
            va.x = acc[mt][nt][0]*dva; va.y = acc[mt][nt][1]*dva;
            vb.x = acc[mt][nt][2]*dvb; vb.y = acc[mt][nt][3]*dvb;
            *(float2*)(opa + (size_t)yy*WW + xx) = va;
            *(float2*)(opb + (size_t)yy*WW + xx) = vb;
        }
    }
}

// ---------------- launch --------------------------------------------------------
extern "C" void kernel_launch(void* const* d_in, const int* in_sizes, int n_in,
                              void* d_out, int out_size) {
    const float *x = nullptr, *style = nullptr, *weight = nullptr, *mod_w = nullptr;
    for (int i = 0; i < n_in; i++){
        switch (in_sizes[i]){
            case Bsz*CIN*HH*WW:   x      = (const float*)d_in[i]; break;
            case Bsz*CIN:         style  = (const float*)d_in[i]; break;
            case COUT*CIN*KAREA:  weight = (const float*)d_in[i]; break;
            case CIN*CIN:         mod_w  = (const float*)d_in[i]; break;
        }
    }
    float* out = (float*)d_out;

    cudaFuncSetAttribute(k_conv_mma, cudaFuncAttributeMaxDynamicSharedMemorySize, SMEM_SZ);

    k_style<<<Bsz, CIN>>>(style, mod_w);
    k_prep2<<<PACKW_BLKS + PREPX_BLKS + DEMOD_BLKS, 256>>>(weight, x);

    dim3 grid(HH/2, COUT/128, Bsz);      // 32 x 4 x 8 = 1024 CTAs
    k_conv_mma<<<grid, 256, SMEM_SZ>>>(out);
}

// round 8
// speedup vs baseline: 1.7117x; 1.2890x over previous
#include <cuda_runtime.h>
#include <cuda_fp16.h>
#include <cstdint>
#include <math.h>

#define Bsz   8
#define CIN   512
#define COUT  512
#define HH    64
#define WW    64
#define KAREA 9
#define RED   (CIN*KAREA)

#define BK      64
#define NCHUNK  (KAREA*(CIN/BK))   // 72
#define XPAD_H  66
#define XROW    64
#define XPLANE  (XPAD_H*XROW)      // 4224

// ---------------- static device scratch --------------------------------------
__device__ float  g_S[Bsz*CIN];
__device__ float  g_D[Bsz*COUT];
__device__ __half g_Ah[(size_t)KAREA*COUT*CIN];        // [sh][o][i]
__device__ __half g_Xh[(size_t)3*Bsz*CIN*XPLANE];      // [kx][b][ci][y+1][x], pads stay 0

// ---------------- helpers ------------------------------------------------------
__device__ __forceinline__ uint32_t smem_u32(const void* p){
    uint32_t a;
    asm("{ .reg .u64 t; cvta.to.shared.u64 t, %1; cvt.u32.u64 %0, t; }" : "=r"(a) : "l"(p));
    return a;
}
__device__ __forceinline__ void cp16(uint32_t dst, const void* src){
    asm volatile("cp.async.cg.shared.global [%0], [%1], 16;" :: "r"(dst), "l"(src));
}
__device__ __forceinline__ void ldsm_x4(uint32_t* r, uint32_t addr){
    asm volatile("ldmatrix.sync.aligned.m8n8.x4.shared.b16 {%0,%1,%2,%3}, [%4];"
                 : "=r"(r[0]),"=r"(r[1]),"=r"(r[2]),"=r"(r[3]) : "r"(addr));
}
__device__ __forceinline__ void ldsm_x4t(uint32_t* r, uint32_t addr){
    asm volatile("ldmatrix.sync.aligned.m8n8.x4.trans.shared.b16 {%0,%1,%2,%3}, [%4];"
                 : "=r"(r[0]),"=r"(r[1]),"=r"(r[2]),"=r"(r[3]) : "r"(addr));
}
__device__ __forceinline__ void mma_f16(float* c, const uint32_t* a, const uint32_t* b){
    asm volatile("mma.sync.aligned.m16n8k16.row.col.f32.f16.f16.f32 "
        "{%0,%1,%2,%3}, {%4,%5,%6,%7}, {%8,%9}, {%0,%1,%2,%3};"
        : "+f"(c[0]),"+f"(c[1]),"+f"(c[2]),"+f"(c[3])
        : "r"(a[0]),"r"(a[1]),"r"(a[2]),"r"(a[3]), "r"(b[0]),"r"(b[1]));
}
__device__ __forceinline__ uint32_t h2pack(__half a, __half b){
    __half2 t = __halves2half2(a, b);
    return *(uint32_t*)&t;
}

// ---------------- prep kernel 1: style modulation (warp per output) ------------
// s[b][i] = dot(style[b,:], mod_w[i,:]). 4096 outputs, 1 warp each.
__global__ void k_style(const float* __restrict__ style, const float* __restrict__ mw){
    int gw   = blockIdx.x*8 + (threadIdx.x >> 5);   // 0..4095
    int lane = threadIdx.x & 31;
    int b = gw >> 9;
    int i = gw & 511;
    const float4* row = (const float4*)(mw + (size_t)i*CIN) + lane;     // stride 32 float4
    const float4* st  = (const float4*)(style + (size_t)b*CIN) + lane;
    float acc = 0.f;
#pragma unroll
    for (int j = 0; j < 4; j++){
        float4 r = row[j*32];
        float4 s = st[j*32];
        acc += r.x*s.x + r.y*s.y + r.z*s.z + r.w*s.w;
    }
#pragma unroll
    for (int off = 16; off; off >>= 1) acc += __shfl_xor_sync(~0u, acc, off);
    if (!lane) g_S[gw] = acc;
}

// ---------------- prep kernel 2: fused packw | prepx | demod -------------------
#define PACKW_BLKS ((KAREA*COUT*CIN)/256)          // 9216
#define PREPX_BLKS ((Bsz*CIN*HH*WW)/(8*256))       // 8192
#define DEMOD_BLKS ((Bsz*COUT)/8)                  // 512

__global__ void k_prep2(const float* __restrict__ w, const float* __restrict__ x){
    int blk = blockIdx.x;
    if (blk < PACKW_BLKS){
        int gid = blk*256 + threadIdx.x;
        int i = gid & 511;
        int o = (gid >> 9) & 511;
        int k = gid >> 18;
        g_Ah[((size_t)k*COUT + o)*CIN + i] = __float2half_rn(w[((size_t)o*CIN + i)*KAREA + k]);
        return;
    }
    blk -= PACKW_BLKS;
    if (blk < PREPX_BLKS){
        int gid = blk*256 + threadIdx.x;
        int t  = gid & 7;
        int y  = (gid >> 3) & 63;
        int ci = (gid >> 9) & 511;
        int b  = gid >> 18;
        float s = g_S[b*CIN + ci];
        const float4* src = (const float4*)(x + (((size_t)(b*CIN + ci)*64 + y)<<6) + (t<<3));
        float4 f0 = src[0], f1 = src[1];
        float v0=f0.x*s, v1=f0.y*s, v2=f0.z*s, v3=f0.w*s;
        float v4=f1.x*s, v5=f1.y*s, v6=f1.z*s, v7=f1.w*s;
        __half h0=__float2half_rn(v0), h1=__float2half_rn(v1),
               h2=__float2half_rn(v2), h3=__float2half_rn(v3),
               h4=__float2half_rn(v4), h5=__float2half_rn(v5),
               h6=__float2half_rn(v6), h7=__float2half_rn(v7);
        float pl = __shfl_up_sync(~0u,  v7, 1);
        float nf = __shfl_down_sync(~0u, v0, 1);
        __half hpl = (t==0) ? __float2half_rn(0.f) : __float2half_rn(pl);
        __half hnf = (t==7) ? __float2half_rn(0.f) : __float2half_rn(nf);
        size_t rowOff = (size_t)(b*CIN + ci)*XPLANE + (size_t)(y+1)*XROW + (t<<3);
        const size_t kxStride = (size_t)Bsz*CIN*XPLANE;
        uint4 c1 = { h2pack(h0,h1), h2pack(h2,h3), h2pack(h4,h5), h2pack(h6,h7) };
        uint4 c0 = { h2pack(hpl,h0), h2pack(h1,h2), h2pack(h3,h4), h2pack(h5,h6) };
        uint4 c2 = { h2pack(h1,h2), h2pack(h3,h4), h2pack(h5,h6), h2pack(h7,hnf) };
        *(uint4*)(g_Xh + rowOff)              = c0;
        *(uint4*)(g_Xh + kxStride + rowOff)   = c1;
        *(uint4*)(g_Xh + 2*kxStride + rowOff) = c2;
        return;
    }
    blk -= PREPX_BLKS;
    {   // demod: one warp per (b,o)
        int gw   = blk*8 + (threadIdx.x >> 5);
        int lane = threadIdx.x & 31;
        int b = gw >> 9, o = gw & 511;
        const float* wr = w + (size_t)o*RED;
        const float* sr = g_S + b*CIN;
        float sum = 0.f;
        for (int idx = lane; idx < RED; idx += 32){
            float m = wr[idx]*sr[idx/9];
            sum += m*m;
        }
#pragma unroll
        for (int off = 16; off; off >>= 1) sum += __shfl_xor_sync(~0u, sum, off);
        if (!lane)
            g_D[gw] = rsqrtf((float)RED) * rsqrtf(sum/(float)RED + 1e-8f);
    }
}

// ---------------- main mma.sync kernel ------------------------------------------
// CTA: 128 couts x 128 px (2 image rows). 8 warps (2m x 4n), warp tile 64x32.
// BK=64, 72 chunks, 3-stage cp.async pipeline, ONE __syncthreads per chunk.

#define APAD   72                    // halfs per A smem row (144B)
#define BPAD   136                   // halfs per B smem row (272B)
#define A_ST   (128*APAD*2)          // 18432 B
#define B_ST   (BK*BPAD*2)           // 17408 B
#define STAGE  (A_ST + B_ST)         // 35840 B
#define SMEM_SZ (3*STAGE)            // 107520 B

__global__ void __launch_bounds__(256, 2)
k_conv_mma(float* __restrict__ out)
{
    extern __shared__ __align__(16) char smraw[];
    const uint32_t s0 = smem_u32(smraw);

    const int tid  = threadIdx.x;
    const int lane = tid & 31;
    const int wid  = tid >> 5;
    const int wm   = wid >> 2;
    const int wn   = wid & 3;

    const int b   = blockIdx.z;
    const int co0 = blockIdx.y << 7;
    const int y0  = blockIdx.x << 1;

    float acc[4][4][4];
#pragma unroll
    for (int mt = 0; mt < 4; mt++)
#pragma unroll
        for (int nt = 0; nt < 4; nt++)
#pragma unroll
            for (int r = 0; r < 4; r++) acc[mt][nt][r] = 0.f;

    auto load_chunk = [&](int ch, int buf){
        int sh  = ch >> 3;
        int ci0 = (ch & 7) << 6;
        int ky  = sh / 3;
        int kx  = sh - ky*3;
        const __half* aSrc = g_Ah + ((size_t)sh*COUT + co0)*CIN + ci0;
        const __half* xSrc = g_Xh + (((size_t)kx*Bsz + b)*CIN + ci0)*XPLANE
                           + (size_t)(y0 + ky)*XROW;
        uint32_t dA = s0 + buf*STAGE;
        uint32_t dB = dA + A_ST;
#pragma unroll
        for (int it = 0; it < 8; it++){
            int idx = tid + (it << 8);
            if (idx < 1024){                      // A: 128 rows x 128B
                int m = idx >> 3, q = idx & 7;
                cp16(dA + m*(APAD*2) + q*16, aSrc + (size_t)m*CIN + (q<<3));
            } else {                              // B: 64 rows x 256B
                int i2 = idx - 1024;
                int k  = i2 >> 4;
                int q  = i2 & 15;
                cp16(dB + k*(BPAD*2) + q*16, xSrc + (size_t)k*XPLANE + (q<<3));
            }
        }
        asm volatile("cp.async.commit_group;");
    };

    load_chunk(0, 0);
    load_chunk(1, 1);

    for (int c = 0; c < NCHUNK; c++){
        if (c < NCHUNK-1) asm volatile("cp.async.wait_group 1;");
        else              asm volatile("cp.async.wait_group 0;");
        __syncthreads();

        if (c + 2 < NCHUNK) load_chunk(c+2, (c+2) % 3);

        const uint32_t aBase = s0 + (c % 3)*STAGE;
        const uint32_t bBase = aBase + A_ST;
#pragma unroll
        for (int ks = 0; ks < 4; ks++){
            uint32_t afr[4][4], bfr[2][4];
#pragma unroll
            for (int mt = 0; mt < 4; mt++){
                int row = wm*64 + mt*16 + (lane & 15);
                int col = ks*16 + ((lane >> 4) << 3);
                ldsm_x4(afr[mt], aBase + (row*APAD + col)*2);
            }
#pragma unroll
            for (int np = 0; np < 2; np++){
                int g  = lane >> 3;
                int lr = lane & 7;
                int row = ks*16 + ((g & 1) << 3) + lr;
                int col = wn*32 + np*16 + ((g >> 1) << 3);
                ldsm_x4t(bfr[np], bBase + (row*BPAD + col)*2);
            }
#pragma unroll
            for (int mt = 0; mt < 4; mt++)
#pragma unroll
                for (int nt = 0; nt < 4; nt++)
                    mma_f16(acc[mt][nt], afr[mt], &bfr[nt>>1][(nt&1)*2]);
        }
    }

    // ---- epilogue: scale*demod, store ----
    const int row0 = lane >> 2;
    const int col0 = (lane & 3) << 1;
#pragma unroll
    for (int mt = 0; mt < 4; mt++){
        int cout_a = co0 + wm*64 + mt*16 + row0;
        int cout_b = cout_a + 8;
        float dva = g_D[b*COUT + cout_a];
        float dvb = g_D[b*COUT + cout_b];
        float* opa = out + ((size_t)(b*COUT + cout_a)*HH + y0)*WW;
        float* opb = out + ((size_t)(b*COUT + cout_b)*HH + y0)*WW;
#pragma unroll
        for (int nt = 0; nt < 4; nt++){
            int n  = wn*32 + nt*8 + col0;
            int yy = n >> 6;
            int xx = n & 63;
            float2 va, vb;
            va.x = acc[mt][nt][0]*dva; va.y = acc[mt][nt][1]*dva;
            vb.x = acc[mt][nt][2]*dvb; vb.y = acc[mt][nt][3]*dvb;
            *(float2*)(opa + (size_t)yy*WW + xx) = va;
            *(float2*)(opb + (size_t)yy*WW + xx) = vb;
        }
    }
}

// ---------------- launch --------------------------------------------------------
extern "C" void kernel_launch(void* const* d_in, const int* in_sizes, int n_in,
                              void* d_out, int out_size) {
    const float *x = nullptr, *style = nullptr, *weight = nullptr, *mod_w = nullptr;
    for (int i = 0; i < n_in; i++){
        switch (in_sizes[i]){
            case Bsz*CIN*HH*WW:   x      = (const float*)d_in[i]; break;
            case Bsz*CIN:         style  = (const float*)d_in[i]; break;
            case COUT*CIN*KAREA:  weight = (const float*)d_in[i]; break;
            case CIN*CIN:         mod_w  = (const float*)d_in[i]; break;
        }
    }
    float* out = (float*)d_out;

    cudaFuncSetAttribute(k_conv_mma, cudaFuncAttributeMaxDynamicSharedMemorySize, SMEM_SZ);

    k_style<<<(Bsz*CIN)/8, 256>>>(style, mod_w);
    k_prep2<<<PACKW_BLKS + PREPX_BLKS + DEMOD_BLKS, 256>>>(weight, x);

    dim3 grid(HH/2, COUT/128, Bsz);      // 32 x 4 x 8 = 1024 CTAs
    k_conv_mma<<<grid, 256, SMEM_SZ>>>(out);
}

// round 9
// speedup vs baseline: 1.7428x; 1.0182x over previous
#include <cuda_runtime.h>
#include <cuda_fp16.h>
#include <cstdint>
#include <math.h>

#define Bsz   8
#define CIN   512
#define COUT  512
#define HH    64
#define WW    64
#define KAREA 9
#define RED   (CIN*KAREA)

#define BK      64
#define NCHUNK  (KAREA*(CIN/BK))   // 72
#define XPAD_H  66
#define XROW    64
#define XPLANE  (XPAD_H*XROW)      // 4224

// ---------------- static device scratch --------------------------------------
__device__ float  g_S[Bsz*CIN];
__device__ float  g_S2[Bsz*CIN];
__device__ float  g_D[Bsz*COUT];
__device__ __half g_Ah[(size_t)COUT*KAREA*CIN];        // [o][k][i]
__device__ __half g_Xh[(size_t)3*Bsz*CIN*XPLANE];      // [kx][b][ci][y+1][x], pads stay 0

// ---------------- helpers ------------------------------------------------------
__device__ __forceinline__ uint32_t smem_u32(const void* p){
    uint32_t a;
    asm("{ .reg .u64 t; cvta.to.shared.u64 t, %1; cvt.u32.u64 %0, t; }" : "=r"(a) : "l"(p));
    return a;
}
__device__ __forceinline__ void cp16(uint32_t dst, const void* src){
    asm volatile("cp.async.cg.shared.global [%0], [%1], 16;" :: "r"(dst), "l"(src));
}
__device__ __forceinline__ void ldsm_x4(uint32_t* r, uint32_t addr){
    asm volatile("ldmatrix.sync.aligned.m8n8.x4.shared.b16 {%0,%1,%2,%3}, [%4];"
                 : "=r"(r[0]),"=r"(r[1]),"=r"(r[2]),"=r"(r[3]) : "r"(addr));
}
__device__ __forceinline__ void ldsm_x4t(uint32_t* r, uint32_t addr){
    asm volatile("ldmatrix.sync.aligned.m8n8.x4.trans.shared.b16 {%0,%1,%2,%3}, [%4];"
                 : "=r"(r[0]),"=r"(r[1]),"=r"(r[2]),"=r"(r[3]) : "r"(addr));
}
__device__ __forceinline__ void mma_f16(float* c, const uint32_t* a, const uint32_t* b){
    asm volatile("mma.sync.aligned.m16n8k16.row.col.f32.f16.f16.f32 "
        "{%0,%1,%2,%3}, {%4,%5,%6,%7}, {%8,%9}, {%0,%1,%2,%3};"
        : "+f"(c[0]),"+f"(c[1]),"+f"(c[2]),"+f"(c[3])
        : "r"(a[0]),"r"(a[1]),"r"(a[2]),"r"(a[3]), "r"(b[0]),"r"(b[1]));
}
__device__ __forceinline__ uint32_t h2pack(__half a, __half b){
    __half2 t = __halves2half2(a, b);
    return *(uint32_t*)&t;
}

// ---------------- prep 1: style modulation (warp per output) -------------------
__global__ void k_style(const float* __restrict__ style, const float* __restrict__ mw){
    int gw   = blockIdx.x*8 + (threadIdx.x >> 5);
    int lane = threadIdx.x & 31;
    int b = gw >> 9;
    int i = gw & 511;
    const float4* row = (const float4*)(mw + (size_t)i*CIN) + lane;
    const float4* st  = (const float4*)(style + (size_t)b*CIN) + lane;
    float acc = 0.f;
#pragma unroll
    for (int j = 0; j < 4; j++){
        float4 r = row[j*32];
        float4 s = st[j*32];
        acc += r.x*s.x + r.y*s.y + r.z*s.z + r.w*s.w;
    }
#pragma unroll
    for (int off = 16; off; off >>= 1) acc += __shfl_xor_sync(~0u, acc, off);
    if (!lane){ g_S[gw] = acc; g_S2[gw] = acc*acc; }
}

// ---------------- prep 2a: per-cout weight pack + fused demod -------------------
// One block per o. Coalesced read of w[o] (4608 fp32), coalesced write of
// g_Ah[o] ([k][i] halves), demod via q[i] = sum_k w^2 dotted with s^2.
__global__ void __launch_bounds__(256)
k_prep_o(const float* __restrict__ w){
    __shared__ float smw[RED];        // 18KB
    __shared__ float q[CIN];          // 2KB
    __shared__ float red8[8][8];
    const int o   = blockIdx.x;
    const int tid = threadIdx.x;
    const float4* src = (const float4*)(w + (size_t)o*RED);
#pragma unroll
    for (int it = 0; it < RED/4/256 + 1; it++){      // 1152 float4
        int idx = tid + it*256;
        if (idx < RED/4) ((float4*)smw)[idx] = src[idx];
    }
    __syncthreads();

    // pack: g_Ah[o][k][i], consecutive tid -> consecutive i (coalesced 2B writes)
    __half* dst = g_Ah + (size_t)o*RED;
#pragma unroll
    for (int it = 0; it < RED/256; it++){            // 18 iters
        int idx = tid + it*256;
        int k = idx >> 9;
        int i = idx & 511;
        dst[idx] = __float2half_rn(smw[i*KAREA + k]);
    }
    // q[i] = sum_k w^2  (each thread does 2 i's)
#pragma unroll
    for (int it = 0; it < 2; it++){
        int i = tid + it*256;
        float s = 0.f;
#pragma unroll
        for (int k = 0; k < KAREA; k++){ float v = smw[i*KAREA + k]; s += v*v; }
        q[i] = s;
    }
    __syncthreads();

    // demod for all 8 batches: warp wb handles b = wb
    {
        int wb   = tid >> 5;
        int lane = tid & 31;
        const float* s2 = g_S2 + wb*CIN;
        float sum = 0.f;
#pragma unroll
        for (int j = 0; j < 16; j++){
            int i = lane + j*32;
            sum += q[i]*s2[i];
        }
#pragma unroll
        for (int off = 16; off; off >>= 1) sum += __shfl_xor_sync(~0u, sum, off);
        if (!lane)
            g_D[wb*COUT + o] = rsqrtf((float)RED) * rsqrtf(sum/(float)RED + 1e-8f);
        (void)red8;
    }
}

// ---------------- prep 2b: x modulate + shift-expand ---------------------------
__global__ void k_prepx(const float* __restrict__ x){
    int gid = blockIdx.x*256 + threadIdx.x;
    int t  = gid & 7;
    int y  = (gid >> 3) & 63;
    int ci = (gid >> 9) & 511;
    int b  = gid >> 18;
    float s = g_S[b*CIN + ci];
    const float4* src = (const float4*)(x + (((size_t)(b*CIN + ci)*64 + y)<<6) + (t<<3));
    float4 f0 = src[0], f1 = src[1];
    float v0=f0.x*s, v1=f0.y*s, v2=f0.z*s, v3=f0.w*s;
    float v4=f1.x*s, v5=f1.y*s, v6=f1.z*s, v7=f1.w*s;
    __half h0=__float2half_rn(v0), h1=__float2half_rn(v1),
           h2=__float2half_rn(v2), h3=__float2half_rn(v3),
           h4=__float2half_rn(v4), h5=__float2half_rn(v5),
           h6=__float2half_rn(v6), h7=__float2half_rn(v7);
    float pl = __shfl_up_sync(~0u,  v7, 1);
    float nf = __shfl_down_sync(~0u, v0, 1);
    __half hpl = (t==0) ? __float2half_rn(0.f) : __float2half_rn(pl);
    __half hnf = (t==7) ? __float2half_rn(0.f) : __float2half_rn(nf);
    size_t rowOff = (size_t)(b*CIN + ci)*XPLANE + (size_t)(y+1)*XROW + (t<<3);
    const size_t kxStride = (size_t)Bsz*CIN*XPLANE;
    uint4 c1 = { h2pack(h0,h1), h2pack(h2,h3), h2pack(h4,h5), h2pack(h6,h7) };
    uint4 c0 = { h2pack(hpl,h0), h2pack(h1,h2), h2pack(h3,h4), h2pack(h5,h6) };
    uint4 c2 = { h2pack(h1,h2), h2pack(h3,h4), h2pack(h5,h6), h2pack(h7,hnf) };
    *(uint4*)(g_Xh + rowOff)              = c0;
    *(uint4*)(g_Xh + kxStride + rowOff)   = c1;
    *(uint4*)(g_Xh + 2*kxStride + rowOff) = c2;
}

// ---------------- main mma.sync kernel ------------------------------------------
#define APAD   72                    // halfs per A smem row (144B)
#define BPAD   136                   // halfs per B smem row (272B)
#define A_ST   (128*APAD*2)
#define B_ST   (BK*BPAD*2)
#define STAGE  (A_ST + B_ST)         // 35840 B
#define SMEM_SZ (3*STAGE)            // 107520 B

__global__ void __launch_bounds__(256, 2)
k_conv_mma(float* __restrict__ out)
{
    extern __shared__ __align__(16) char smraw[];
    const uint32_t s0 = smem_u32(smraw);

    const int tid  = threadIdx.x;
    const int lane = tid & 31;
    const int wid  = tid >> 5;
    const int wm   = wid >> 2;
    const int wn   = wid & 3;

    const int b   = blockIdx.z;
    const int co0 = blockIdx.y << 7;
    const int y0  = blockIdx.x << 1;

    float acc[4][4][4];
#pragma unroll
    for (int mt = 0; mt < 4; mt++)
#pragma unroll
        for (int nt = 0; nt < 4; nt++)
#pragma unroll
            for (int r = 0; r < 4; r++) acc[mt][nt][r] = 0.f;

    auto load_chunk = [&](int ch, int buf){
        int sh  = ch >> 3;
        int ci0 = (ch & 7) << 6;
        int ky  = sh / 3;
        int kx  = sh - ky*3;
        const __half* aSrc = g_Ah + (size_t)co0*RED + (size_t)sh*CIN + ci0;  // [o][k][i]
        const __half* xSrc = g_Xh + (((size_t)kx*Bsz + b)*CIN + ci0)*XPLANE
                           + (size_t)(y0 + ky)*XROW;
        uint32_t dA = s0 + buf*STAGE;
        uint32_t dB = dA + A_ST;
#pragma unroll
        for (int it = 0; it < 8; it++){
            int idx = tid + (it << 8);
            if (idx < 1024){                      // A: 128 rows (couts) x 128B
                int m = idx >> 3, q = idx & 7;
                cp16(dA + m*(APAD*2) + q*16, aSrc + (size_t)m*RED + (q<<3));
            } else {                              // B: 64 rows x 256B
                int i2 = idx - 1024;
                int k  = i2 >> 4;
                int q  = i2 & 15;
                cp16(dB + k*(BPAD*2) + q*16, xSrc + (size_t)k*XPLANE + (q<<3));
            }
        }
        asm volatile("cp.async.commit_group;");
    };

    load_chunk(0, 0);
    load_chunk(1, 1);

    for (int c = 0; c < NCHUNK; c++){
        if (c < NCHUNK-1) asm volatile("cp.async.wait_group 1;");
        else              asm volatile("cp.async.wait_group 0;");
        __syncthreads();

        if (c + 2 < NCHUNK) load_chunk(c+2, (c+2) % 3);

        const uint32_t aBase = s0 + (c % 3)*STAGE;
        const uint32_t bBase = aBase + A_ST;
#pragma unroll
        for (int ks = 0; ks < 4; ks++){
            uint32_t afr[4][4], bfr[2][4];
#pragma unroll
            for (int mt = 0; mt < 4; mt++){
                int row = wm*64 + mt*16 + (lane & 15);
                int col = ks*16 + ((lane >> 4) << 3);
                ldsm_x4(afr[mt], aBase + (row*APAD + col)*2);
            }
#pragma unroll
            for (int np = 0; np < 2; np++){
                int g  = lane >> 3;
                int lr = lane & 7;
                int row = ks*16 + ((g & 1) << 3) + lr;
                int col = wn*32 + np*16 + ((g >> 1) << 3);
                ldsm_x4t(bfr[np], bBase + (row*BPAD + col)*2);
            }
#pragma unroll
            for (int mt = 0; mt < 4; mt++)
#pragma unroll
                for (int nt = 0; nt < 4; nt++)
                    mma_f16(acc[mt][nt], afr[mt], &bfr[nt>>1][(nt&1)*2]);
        }
    }

    // ---- epilogue ----
    const int row0 = lane >> 2;
    const int col0 = (lane & 3) << 1;
#pragma unroll
    for (int mt = 0; mt < 4; mt++){
        int cout_a = co0 + wm*64 + mt*16 + row0;
        int cout_b = cout_a + 8;
        float dva = g_D[b*COUT + cout_a];
        float dvb = g_D[b*COUT + cout_b];
        float* opa = out + ((size_t)(b*COUT + cout_a)*HH + y0)*WW;
        float* opb = out + ((size_t)(b*COUT + cout_b)*HH + y0)*WW;
#pragma unroll
        for (int nt = 0; nt < 4; nt++){
            int n  = wn*32 + nt*8 + col0;
            int yy = n >> 6;
            int xx = n & 63;
            float2 va, vb;
            va.x = acc[mt][nt][0]*dva; va.y = acc[mt][nt][1]*dva;
            vb.x = acc[mt][nt][2]*dvb; vb.y = acc[mt][nt][3]*dvb;
            *(float2*)(opa + (size_t)yy*WW + xx) = va;
            *(float2*)(opb + (size_t)yy*WW + xx) = vb;
        }
    }
}

// ---------------- launch --------------------------------------------------------
extern "C" void kernel_launch(void* const* d_in, const int* in_sizes, int n_in,
                              void* d_out, int out_size) {
    const float *x = nullptr, *style = nullptr, *weight = nullptr, *mod_w = nullptr;
    for (int i = 0; i < n_in; i++){
        switch (in_sizes[i]){
            case Bsz*CIN*HH*WW:   x      = (const float*)d_in[i]; break;
            case Bsz*CIN:         style  = (const float*)d_in[i]; break;
            case COUT*CIN*KAREA:  weight = (const float*)d_in[i]; break;
            case CIN*CIN:         mod_w  = (const float*)d_in[i]; break;
        }
    }
    float* out = (float*)d_out;

    cudaFuncSetAttribute(k_conv_mma, cudaFuncAttributeMaxDynamicSharedMemorySize, SMEM_SZ);

    k_style<<<(Bsz*CIN)/8, 256>>>(style, mod_w);
    k_prep_o<<<COUT, 256>>>(weight);
    k_prepx<<<(Bsz*CIN*HH*WW)/(8*256), 256>>>(x);

    dim3 grid(HH/2, COUT/128, Bsz);
    k_conv_mma<<<grid, 256, SMEM_SZ>>>(out);
}